// round 6
// baseline (speedup 1.0000x reference)
#include <cuda_runtime.h>
#include <cstdint>

#define TT   128
#define BLK  128
#define EPB  40          // elements per block: 4 warps x 10
#define RSTRIDE 220      // floats per role block in shared

// ---- shared layout (floats) ----
#define FC_OFF 660
#define FW1 (FC_OFF)
#define FB1 (FW1+640)
#define FW2 (FB1+32)
#define FB2 (FW2+1024)
#define FW3 (FB2+32)
#define FB3 (FW3+512)
#define FW4 (FB3+16)
#define FB4 (FW4+256)
#define FW5 (FB4+16)
#define FB5 (FW5+80)
#define S_TOTAL (FB5+5)   // 3273 floats = ~13.1 KB

__device__ __forceinline__ float tanh_fast(float x) {
    float y;
    asm("tanh.approx.f32 %0, %1;" : "=f"(y) : "f"(x));
    return y;
}
// rows pre-scaled by 0.5 at staging: sigm(a) = fma(tanh(a'), 0.5, 0.5)
__device__ __forceinline__ float sigm_pre(float a_half) {
    return fmaf(tanh_fast(a_half), 0.5f, 0.5f);
}

__device__ __forceinline__ void cp_async4(unsigned saddr, const float* g) {
    asm volatile("cp.async.ca.shared.global [%0], [%1], 4;" :: "r"(saddr), "l"(g) : "memory");
}
__device__ __forceinline__ void cp_commit() {
    asm volatile("cp.async.commit_group;" ::: "memory");
}
__device__ __forceinline__ void cp_wait1() {
    asm volatile("cp.async.wait_group 1;" ::: "memory");
}

// One H=5 LSTM cell step. sW: WihT[5][20], WhhT at +100 (i/f/o rows pre-scaled 0.5).
// Bias (pre-scaled) read from shared each step.
__device__ __forceinline__ void cell(const float* __restrict__ sW,
                                     const float* __restrict__ sB,
                                     const float* __restrict__ in,
                                     float* __restrict__ h,
                                     float* __restrict__ c,
                                     bool commit) {
    float g[20];
    {
        const float4* b4 = reinterpret_cast<const float4*>(sB);
        #pragma unroll
        for (int q = 0; q < 5; q++) {
            float4 v = b4[q];
            g[4*q+0] = v.x; g[4*q+1] = v.y; g[4*q+2] = v.z; g[4*q+3] = v.w;
        }
    }
    #pragma unroll
    for (int k = 0; k < 5; k++) {
        float xk = in[k];
        const float4* w4 = reinterpret_cast<const float4*>(sW + k * 20);
        #pragma unroll
        for (int q = 0; q < 5; q++) {
            float4 w = w4[q];
            g[4*q+0] = fmaf(w.x, xk, g[4*q+0]);
            g[4*q+1] = fmaf(w.y, xk, g[4*q+1]);
            g[4*q+2] = fmaf(w.z, xk, g[4*q+2]);
            g[4*q+3] = fmaf(w.w, xk, g[4*q+3]);
        }
    }
    #pragma unroll
    for (int k = 0; k < 5; k++) {
        float hk = h[k];
        const float4* u4 = reinterpret_cast<const float4*>(sW + 100 + k * 20);
        #pragma unroll
        for (int q = 0; q < 5; q++) {
            float4 u = u4[q];
            g[4*q+0] = fmaf(u.x, hk, g[4*q+0]);
            g[4*q+1] = fmaf(u.y, hk, g[4*q+1]);
            g[4*q+2] = fmaf(u.z, hk, g[4*q+2]);
            g[4*q+3] = fmaf(u.w, hk, g[4*q+3]);
        }
    }
    #pragma unroll
    for (int m = 0; m < 5; m++) {
        float ig = sigm_pre(g[m]);
        float fg = sigm_pre(g[5 + m]);
        float gg = tanh_fast(g[10 + m]);
        float og = sigm_pre(g[15 + m]);
        float cm = fmaf(fg, c[m], ig * gg);
        float hm = og * tanh_fast(cm);
        c[m] = commit ? cm : c[m];
        h[m] = commit ? hm : h[m];
    }
}

struct Params {
    const float *x1, *x2;
    const float *Wih1, *Whh1, *bih1, *bhh1;
    const float *Wih2a, *Whh2a, *bih2a, *bhh2a;
    const float *Wih2b, *Whh2b, *bih2b, *bhh2b;
    const float *W1, *b1, *W2, *b2, *W3, *b3, *W4, *b4, *W5, *b5;
    float* out;
    int B;
};

__global__ __launch_bounds__(BLK, 4)
void dynrnn_kernel(Params p) {
    __shared__ float s[S_TOTAL];
    __shared__ float xs[2][20][BLK];   // [buf][chunk element j][lane] — 20.5 KB
    const int tid = threadIdx.x;

    // ---- cooperative weight staging (transposed LSTM weights, role blocks) ----
    // sigmoid-gate rows (j<10 i/f, j>=15 o) pre-scaled by 0.5
    {
        const float* srcs[6] = { p.Wih1, p.Whh1, p.Wih2a, p.Whh2a, p.Wih2b, p.Whh2b };
        const int    offs[6] = { 0, 100, RSTRIDE, RSTRIDE+100, 2*RSTRIDE, 2*RSTRIDE+100 };
        for (int m = 0; m < 6; m++) {
            const float* W = srcs[m];
            int off = offs[m];
            for (int i = tid; i < 100; i += BLK) {
                int j = i / 5, k = i % 5;
                float sc = (j < 10 || j >= 15) ? 0.5f : 1.0f;
                s[off + k * 20 + j] = W[i] * sc;
            }
        }
        for (int i = tid; i < 20; i += BLK) {
            float sc = (i < 10 || i >= 15) ? 0.5f : 1.0f;
            s[0*RSTRIDE + 200 + i] = (p.bih1[i]  + p.bhh1[i])  * sc;
            s[1*RSTRIDE + 200 + i] = (p.bih2a[i] + p.bhh2a[i]) * sc;
            s[2*RSTRIDE + 200 + i] = (p.bih2b[i] + p.bhh2b[i]) * sc;
        }
        for (int i = tid; i < 640;  i += BLK) s[FW1 + i] = p.W1[i];
        for (int i = tid; i < 32;   i += BLK) s[FB1 + i] = p.b1[i];
        for (int i = tid; i < 1024; i += BLK) s[FW2 + i] = p.W2[i];
        for (int i = tid; i < 32;   i += BLK) s[FB2 + i] = p.b2[i];
        for (int i = tid; i < 512;  i += BLK) s[FW3 + i] = p.W3[i];
        for (int i = tid; i < 16;   i += BLK) s[FB3 + i] = p.b3[i];
        for (int i = tid; i < 256;  i += BLK) s[FW4 + i] = p.W4[i];
        for (int i = tid; i < 16;   i += BLK) s[FB4 + i] = p.b4[i];
        for (int i = tid; i < 80;   i += BLK) s[FW5 + i] = p.W5[i];
        for (int i = tid; i < 5;    i += BLK) s[FB5 + i] = p.b5[i];
    }
    __syncthreads();

    // ---- lane/role mapping: 3 lanes per element, 10 elements per warp ----
    const int l   = tid & 31;
    const int grp = l / 3;           // 0..9
    const int r   = l - 3 * grp;     // 0: lstm1, 1: lstm2a, 2: lstm2b
    const bool lane_ok = (l < 30);

    const int e = blockIdx.x * EPB + (tid >> 5) * 10 + grp;
    const bool valid = lane_ok && (e < p.B);
    const int ec = (e < p.B) ? e : (p.B - 1);

    const float* __restrict__ xp = ((r == 1) ? p.x2 : p.x1) + (size_t)ec * (TT * 5);
    const float* __restrict__ sW = s + r * RSTRIDE;
    const float* __restrict__ sB = sW + 200;
    const bool isr2 = (r == 2);

    const unsigned xs_base = (unsigned)__cvta_generic_to_shared(&xs[0][0][0]);

    float h[5], c[5], nh[5];
    #pragma unroll
    for (int m = 0; m < 5; m++) { h[m] = 0.0f; c[m] = 0.0f; nh[m] = 0.0f; }

    // prefetch chunk 0 into buf 0 (each thread fills its own column)
    {
        const float* src = xp;
        unsigned dst = xs_base + (unsigned)tid * 4u;
        #pragma unroll
        for (int j = 0; j < 20; j++)
            cp_async4(dst + (unsigned)j * (BLK * 4), src + j);
        cp_commit();
    }

    #pragma unroll 1
    for (int it = 0; it < 32; it++) {
        // prefetch next chunk (skipped on last iter; empty commit keeps group count in sync)
        if (it + 1 < 32) {
            const float* src = xp + (it + 1) * 20;
            unsigned dst = xs_base + (unsigned)(((it + 1) & 1) * 20 * BLK + tid) * 4u;
            #pragma unroll
            for (int j = 0; j < 20; j++)
                cp_async4(dst + (unsigned)j * (BLK * 4), src + j);
        }
        cp_commit();
        cp_wait1();   // chunk `it` resident

        const int b = it & 1;
        #pragma unroll
        for (int tl = 0; tl < 4; tl++) {
            float in[5];
            #pragma unroll
            for (int j = 0; j < 5; j++) {
                float v = xs[b][tl * 5 + j][tid];
                in[j] = isr2 ? nh[j] : v;
            }
            bool commit = !(isr2 && (it == 0) && (tl == 0));
            cell(sW, sB, in, h, c, commit);
            #pragma unroll
            for (int j = 0; j < 5; j++) nh[j] = __shfl_up_sync(0xFFFFFFFFu, h[j], 1);
        }
    }

    // role-2 drains the pipeline: final step consumes h2a(127)
    if (isr2) {
        cell(sW, sB, nh, h, c, true);
    }

    // ---- gather results onto role-0 lanes ----
    // last timestep inputs live in buf 1 (chunk 31), tl=3 → offsets 15..19
    float lastx[5];
    #pragma unroll
    for (int j = 0; j < 5; j++) lastx[j] = xs[1][15 + j][tid];

    float x2l[5], o2[5];
    #pragma unroll
    for (int j = 0; j < 5; j++) {
        x2l[j] = __shfl_down_sync(0xFFFFFFFFu, lastx[j], 1);  // from role 1 (x2 last)
        o2[j]  = __shfl_down_sync(0xFFFFFFFFu, h[j], 2);      // from role 2 (out2)
    }

    if (valid && r == 0) {
        float a0[20];
        #pragma unroll
        for (int j = 0; j < 5; j++) {
            a0[j]      = lastx[j];   // x1 last
            a0[5 + j]  = x2l[j];     // x2 last
            a0[10 + j] = h[j];       // out1
            a0[15 + j] = o2[j];      // out2
        }
        float a1[32];
        #pragma unroll
        for (int j = 0; j < 32; j++) {
            float acc = s[FB1 + j];
            #pragma unroll
            for (int k = 0; k < 20; k++) acc = fmaf(s[FW1 + j * 20 + k], a0[k], acc);
            a1[j] = fmaxf(acc, 0.0f);
        }
        float a2[32];
        #pragma unroll
        for (int j = 0; j < 32; j++) {
            float acc = s[FB2 + j];
            #pragma unroll
            for (int k = 0; k < 32; k++) acc = fmaf(s[FW2 + j * 32 + k], a1[k], acc);
            a2[j] = fmaxf(acc, 0.0f);
        }
        float a3[16];
        #pragma unroll
        for (int j = 0; j < 16; j++) {
            float acc = s[FB3 + j];
            #pragma unroll
            for (int k = 0; k < 32; k++) acc = fmaf(s[FW3 + j * 32 + k], a2[k], acc);
            a3[j] = fmaxf(acc, 0.0f);
        }
        float a4[16];
        #pragma unroll
        for (int j = 0; j < 16; j++) {
            float acc = s[FB4 + j];
            #pragma unroll
            for (int k = 0; k < 16; k++) acc = fmaf(s[FW4 + j * 16 + k], a3[k], acc);
            a4[j] = fmaxf(acc, 0.0f);
        }
        #pragma unroll
        for (int j = 0; j < 5; j++) {
            float acc = s[FB5 + j];
            #pragma unroll
            for (int k = 0; k < 16; k++) acc = fmaf(s[FW5 + j * 16 + k], a4[k], acc);
            p.out[(size_t)e * 5 + j] = acc;
        }
    }
}

extern "C" void kernel_launch(void* const* d_in, const int* in_sizes, int n_in,
                              void* d_out, int out_size) {
    Params p;
    p.x1    = (const float*)d_in[0];
    p.x2    = (const float*)d_in[1];
    p.Wih1  = (const float*)d_in[2];
    p.Whh1  = (const float*)d_in[3];
    p.bih1  = (const float*)d_in[4];
    p.bhh1  = (const float*)d_in[5];
    p.Wih2a = (const float*)d_in[6];
    p.Whh2a = (const float*)d_in[7];
    p.bih2a = (const float*)d_in[8];
    p.bhh2a = (const float*)d_in[9];
    p.Wih2b = (const float*)d_in[10];
    p.Whh2b = (const float*)d_in[11];
    p.bih2b = (const float*)d_in[12];
    p.bhh2b = (const float*)d_in[13];
    p.W1 = (const float*)d_in[14];  p.b1 = (const float*)d_in[15];
    p.W2 = (const float*)d_in[16];  p.b2 = (const float*)d_in[17];
    p.W3 = (const float*)d_in[18];  p.b3 = (const float*)d_in[19];
    p.W4 = (const float*)d_in[20];  p.b4 = (const float*)d_in[21];
    p.W5 = (const float*)d_in[22];  p.b5 = (const float*)d_in[23];
    p.out = (float*)d_out;
    p.B   = in_sizes[0] / (TT * 5);

    int grid = (p.B + EPB - 1) / EPB;   // 410 blocks for B=16384
    dynrnn_kernel<<<grid, BLK>>>(p);
}

// round 7
// speedup vs baseline: 1.3225x; 1.3225x over previous
#include <cuda_runtime.h>
#include <cstdint>

#define TT   128
#define BLK  128
#define EPB  40          // elements per block: 4 warps x 10
#define RSTRIDE 220      // floats per role block in shared

// ---- shared layout (floats) ----
#define FC_OFF 660
#define FW1 (FC_OFF)
#define FB1 (FW1+640)
#define FW2 (FB1+32)
#define FB2 (FW2+1024)
#define FW3 (FB2+32)
#define FB3 (FW3+512)
#define FW4 (FB3+16)
#define FB4 (FW4+256)
#define FW5 (FB4+16)
#define FB5 (FW5+80)
#define S_TOTAL (FB5+5)   // 3273 floats = ~13.1 KB

__device__ __forceinline__ float tanh_fast(float x) {
    float y;
    asm("tanh.approx.f32 %0, %1;" : "=f"(y) : "f"(x));
    return y;
}
// rows pre-scaled by 0.5 at staging: sigm(a) = fma(tanh(a'), 0.5, 0.5)
__device__ __forceinline__ float sigm_pre(float a_half) {
    return fmaf(tanh_fast(a_half), 0.5f, 0.5f);
}

// One H=5 LSTM cell step. sW: WihT[5][20], WhhT at +100 (i/f/o rows pre-scaled 0.5).
// Bias (pre-scaled) read from shared (float4), folded as the g init.
__device__ __forceinline__ void cell(const float* __restrict__ sW,
                                     const float* __restrict__ sB,
                                     const float* __restrict__ in,
                                     float* __restrict__ h,
                                     float* __restrict__ c,
                                     bool commit) {
    float g[20];
    {
        const float4* b4 = reinterpret_cast<const float4*>(sB);
        #pragma unroll
        for (int q = 0; q < 5; q++) {
            float4 v = b4[q];
            g[4*q+0] = v.x; g[4*q+1] = v.y; g[4*q+2] = v.z; g[4*q+3] = v.w;
        }
    }
    #pragma unroll
    for (int k = 0; k < 5; k++) {
        float xk = in[k];
        const float4* w4 = reinterpret_cast<const float4*>(sW + k * 20);
        #pragma unroll
        for (int q = 0; q < 5; q++) {
            float4 w = w4[q];
            g[4*q+0] = fmaf(w.x, xk, g[4*q+0]);
            g[4*q+1] = fmaf(w.y, xk, g[4*q+1]);
            g[4*q+2] = fmaf(w.z, xk, g[4*q+2]);
            g[4*q+3] = fmaf(w.w, xk, g[4*q+3]);
        }
    }
    #pragma unroll
    for (int k = 0; k < 5; k++) {
        float hk = h[k];
        const float4* u4 = reinterpret_cast<const float4*>(sW + 100 + k * 20);
        #pragma unroll
        for (int q = 0; q < 5; q++) {
            float4 u = u4[q];
            g[4*q+0] = fmaf(u.x, hk, g[4*q+0]);
            g[4*q+1] = fmaf(u.y, hk, g[4*q+1]);
            g[4*q+2] = fmaf(u.z, hk, g[4*q+2]);
            g[4*q+3] = fmaf(u.w, hk, g[4*q+3]);
        }
    }
    #pragma unroll
    for (int m = 0; m < 5; m++) {
        float ig = sigm_pre(g[m]);
        float fg = sigm_pre(g[5 + m]);
        float gg = tanh_fast(g[10 + m]);
        float og = sigm_pre(g[15 + m]);
        float cm = fmaf(fg, c[m], ig * gg);
        float hm = og * tanh_fast(cm);
        c[m] = commit ? cm : c[m];
        h[m] = commit ? hm : h[m];
    }
}

// Load one 2-timestep chunk (10 floats, 8B-aligned) with LDG.64.
__device__ __forceinline__ void load2(float* dst, const float* src) {
    const float2* s2 = reinterpret_cast<const float2*>(src);
    #pragma unroll
    for (int i = 0; i < 5; i++) {
        float2 v = __ldg(s2 + i);
        dst[2*i+0] = v.x; dst[2*i+1] = v.y;
    }
}

struct Params {
    const float *x1, *x2;
    const float *Wih1, *Whh1, *bih1, *bhh1;
    const float *Wih2a, *Whh2a, *bih2a, *bhh2a;
    const float *Wih2b, *Whh2b, *bih2b, *bhh2b;
    const float *W1, *b1, *W2, *b2, *W3, *b3, *W4, *b4, *W5, *b5;
    float* out;
    int B;
};

__global__ __launch_bounds__(BLK, 3)
void dynrnn_kernel(Params p) {
    __shared__ float s[S_TOTAL];
    const int tid = threadIdx.x;

    // ---- cooperative weight staging (transposed LSTM weights, role blocks) ----
    // sigmoid-gate rows (j<10 i/f, j>=15 o) pre-scaled by 0.5
    {
        const float* srcs[6] = { p.Wih1, p.Whh1, p.Wih2a, p.Whh2a, p.Wih2b, p.Whh2b };
        const int    offs[6] = { 0, 100, RSTRIDE, RSTRIDE+100, 2*RSTRIDE, 2*RSTRIDE+100 };
        for (int m = 0; m < 6; m++) {
            const float* W = srcs[m];
            int off = offs[m];
            for (int i = tid; i < 100; i += BLK) {
                int j = i / 5, k = i % 5;
                float sc = (j < 10 || j >= 15) ? 0.5f : 1.0f;
                s[off + k * 20 + j] = W[i] * sc;
            }
        }
        for (int i = tid; i < 20; i += BLK) {
            float sc = (i < 10 || i >= 15) ? 0.5f : 1.0f;
            s[0*RSTRIDE + 200 + i] = (p.bih1[i]  + p.bhh1[i])  * sc;
            s[1*RSTRIDE + 200 + i] = (p.bih2a[i] + p.bhh2a[i]) * sc;
            s[2*RSTRIDE + 200 + i] = (p.bih2b[i] + p.bhh2b[i]) * sc;
        }
        for (int i = tid; i < 640;  i += BLK) s[FW1 + i] = p.W1[i];
        for (int i = tid; i < 32;   i += BLK) s[FB1 + i] = p.b1[i];
        for (int i = tid; i < 1024; i += BLK) s[FW2 + i] = p.W2[i];
        for (int i = tid; i < 32;   i += BLK) s[FB2 + i] = p.b2[i];
        for (int i = tid; i < 512;  i += BLK) s[FW3 + i] = p.W3[i];
        for (int i = tid; i < 16;   i += BLK) s[FB3 + i] = p.b3[i];
        for (int i = tid; i < 256;  i += BLK) s[FW4 + i] = p.W4[i];
        for (int i = tid; i < 16;   i += BLK) s[FB4 + i] = p.b4[i];
        for (int i = tid; i < 80;   i += BLK) s[FW5 + i] = p.W5[i];
        for (int i = tid; i < 5;    i += BLK) s[FB5 + i] = p.b5[i];
    }
    __syncthreads();

    // ---- lane/role mapping: 3 lanes per element, 10 elements per warp ----
    const int l   = tid & 31;
    const int grp = l / 3;           // 0..9
    const int r   = l - 3 * grp;     // 0: lstm1, 1: lstm2a, 2: lstm2b
    const bool lane_ok = (l < 30);

    const int e = blockIdx.x * EPB + (tid >> 5) * 10 + grp;
    const bool valid = lane_ok && (e < p.B);
    const int ec = (e < p.B) ? e : (p.B - 1);

    const float* __restrict__ xp = ((r == 1) ? p.x2 : p.x1) + (size_t)ec * (TT * 5);
    const float* __restrict__ sW = s + r * RSTRIDE;
    const float* __restrict__ sB = sW + 200;
    const bool isr2 = (r == 2);

    float h[5], c[5], nh[5];
    #pragma unroll
    for (int m = 0; m < 5; m++) { h[m] = 0.0f; c[m] = 0.0f; nh[m] = 0.0f; }

    float A[10], Bb[10];     // 2-timestep double buffers
    load2(A, xp);            // chunk 0 (steps 0,1)

    // ---- peeled first pair (chunks 0,1) — loop-invariant warm-up select ----
    {
        load2(Bb, xp + 10);                       // chunk 1
        {
            float in[5];
            #pragma unroll
            for (int j = 0; j < 5; j++) in[j] = isr2 ? nh[j] : A[j];
            cell(sW, sB, in, h, c, !isr2);        // r2 warm-up: no commit
            #pragma unroll
            for (int j = 0; j < 5; j++) nh[j] = __shfl_up_sync(0xFFFFFFFFu, h[j], 1);
        }
        {
            float in[5];
            #pragma unroll
            for (int j = 0; j < 5; j++) in[j] = isr2 ? nh[j] : A[5 + j];
            cell(sW, sB, in, h, c, true);
            #pragma unroll
            for (int j = 0; j < 5; j++) nh[j] = __shfl_up_sync(0xFFFFFFFFu, h[j], 1);
        }
        load2(A, xp + 20);                        // chunk 2
        #pragma unroll
        for (int tl = 0; tl < 2; tl++) {
            float in[5];
            #pragma unroll
            for (int j = 0; j < 5; j++) in[j] = isr2 ? nh[j] : Bb[tl * 5 + j];
            cell(sW, sB, in, h, c, true);
            #pragma unroll
            for (int j = 0; j < 5; j++) nh[j] = __shfl_up_sync(0xFFFFFFFFu, h[j], 1);
        }
    }

    // ---- main loop: pairs k=1..31 handle chunks (2k, 2k+1); A holds chunk 2k ----
    #pragma unroll 1
    for (int k = 1; k < 32; k++) {
        load2(Bb, xp + (2 * k + 1) * 10);         // chunk 2k+1
        #pragma unroll
        for (int tl = 0; tl < 2; tl++) {
            float in[5];
            #pragma unroll
            for (int j = 0; j < 5; j++) in[j] = isr2 ? nh[j] : A[tl * 5 + j];
            cell(sW, sB, in, h, c, true);
            #pragma unroll
            for (int j = 0; j < 5; j++) nh[j] = __shfl_up_sync(0xFFFFFFFFu, h[j], 1);
        }
        int ci = 2 * k + 2; if (ci > 63) ci = 63; // clamped redundant load on last iter
        load2(A, xp + ci * 10);
        #pragma unroll
        for (int tl = 0; tl < 2; tl++) {
            float in[5];
            #pragma unroll
            for (int j = 0; j < 5; j++) in[j] = isr2 ? nh[j] : Bb[tl * 5 + j];
            cell(sW, sB, in, h, c, true);
            #pragma unroll
            for (int j = 0; j < 5; j++) nh[j] = __shfl_up_sync(0xFFFFFFFFu, h[j], 1);
        }
    }

    // role-2 drains the pipeline: final step consumes h2a(127)
    if (isr2) {
        cell(sW, sB, nh, h, c, true);
    }

    // ---- gather results onto role-0 lanes ----
    // Bb holds chunk 63 (steps 126,127): last-step inputs at Bb[5..9]
    float x2l[5], o2[5];
    #pragma unroll
    for (int j = 0; j < 5; j++) {
        x2l[j] = __shfl_down_sync(0xFFFFFFFFu, Bb[5 + j], 1);  // from role 1 (x2 last)
        o2[j]  = __shfl_down_sync(0xFFFFFFFFu, h[j], 2);       // from role 2 (out2)
    }

    if (valid && r == 0) {
        float a0[20];
        #pragma unroll
        for (int j = 0; j < 5; j++) {
            a0[j]      = Bb[5 + j];  // x1 last
            a0[5 + j]  = x2l[j];     // x2 last
            a0[10 + j] = h[j];       // out1
            a0[15 + j] = o2[j];      // out2
        }
        float a1[32];
        #pragma unroll
        for (int j = 0; j < 32; j++) {
            float acc = s[FB1 + j];
            #pragma unroll
            for (int k = 0; k < 20; k++) acc = fmaf(s[FW1 + j * 20 + k], a0[k], acc);
            a1[j] = fmaxf(acc, 0.0f);
        }
        float a2[32];
        #pragma unroll
        for (int j = 0; j < 32; j++) {
            float acc = s[FB2 + j];
            #pragma unroll
            for (int k = 0; k < 32; k++) acc = fmaf(s[FW2 + j * 32 + k], a1[k], acc);
            a2[j] = fmaxf(acc, 0.0f);
        }
        float a3[16];
        #pragma unroll
        for (int j = 0; j < 16; j++) {
            float acc = s[FB3 + j];
            #pragma unroll
            for (int k = 0; k < 32; k++) acc = fmaf(s[FW3 + j * 32 + k], a2[k], acc);
            a3[j] = fmaxf(acc, 0.0f);
        }
        float a4[16];
        #pragma unroll
        for (int j = 0; j < 16; j++) {
            float acc = s[FB4 + j];
            #pragma unroll
            for (int k = 0; k < 16; k++) acc = fmaf(s[FW4 + j * 16 + k], a3[k], acc);
            a4[j] = fmaxf(acc, 0.0f);
        }
        #pragma unroll
        for (int j = 0; j < 5; j++) {
            float acc = s[FB5 + j];
            #pragma unroll
            for (int k = 0; k < 16; k++) acc = fmaf(s[FW5 + j * 16 + k], a4[k], acc);
            p.out[(size_t)e * 5 + j] = acc;
        }
    }
}

extern "C" void kernel_launch(void* const* d_in, const int* in_sizes, int n_in,
                              void* d_out, int out_size) {
    Params p;
    p.x1    = (const float*)d_in[0];
    p.x2    = (const float*)d_in[1];
    p.Wih1  = (const float*)d_in[2];
    p.Whh1  = (const float*)d_in[3];
    p.bih1  = (const float*)d_in[4];
    p.bhh1  = (const float*)d_in[5];
    p.Wih2a = (const float*)d_in[6];
    p.Whh2a = (const float*)d_in[7];
    p.bih2a = (const float*)d_in[8];
    p.bhh2a = (const float*)d_in[9];
    p.Wih2b = (const float*)d_in[10];
    p.Whh2b = (const float*)d_in[11];
    p.bih2b = (const float*)d_in[12];
    p.bhh2b = (const float*)d_in[13];
    p.W1 = (const float*)d_in[14];  p.b1 = (const float*)d_in[15];
    p.W2 = (const float*)d_in[16];  p.b2 = (const float*)d_in[17];
    p.W3 = (const float*)d_in[18];  p.b3 = (const float*)d_in[19];
    p.W4 = (const float*)d_in[20];  p.b4 = (const float*)d_in[21];
    p.W5 = (const float*)d_in[22];  p.b5 = (const float*)d_in[23];
    p.out = (float*)d_out;
    p.B   = in_sizes[0] / (TT * 5);

    int grid = (p.B + EPB - 1) / EPB;   // 410 blocks for B=16384
    dynrnn_kernel<<<grid, BLK>>>(p);
}

// round 8
// speedup vs baseline: 2.9779x; 2.2518x over previous
#include <cuda_runtime.h>
#include <cstdint>

#define TT   128
#define BLK  128
#define EPB  40          // elements per block: 4 warps x 10
#define RSTRIDE 220      // floats per role block in shared

// ---- shared layout (floats) ----
#define FC_OFF 660
#define FW1 (FC_OFF)
#define FB1 (FW1+640)
#define FW2 (FB1+32)
#define FB2 (FW2+1024)
#define FW3 (FB2+32)
#define FB3 (FW3+512)
#define FW4 (FB3+16)
#define FB4 (FW4+256)
#define FW5 (FB4+16)
#define FB5 (FW5+80)
#define S_TOTAL (FB5+5)   // 3273 floats = ~13.1 KB

typedef unsigned long long u64;

__device__ __forceinline__ float tanh_fast(float x) {
    float y;
    asm("tanh.approx.f32 %0, %1;" : "=f"(y) : "f"(x));
    return y;
}
// rows pre-scaled by 0.5 at staging: sigm(a) = fma(tanh(a'), 0.5, 0.5)
__device__ __forceinline__ float sigm_pre(float a_half) {
    return fmaf(tanh_fast(a_half), 0.5f, 0.5f);
}

// Packed dual FMA on register pairs (no per-op repacking).
__device__ __forceinline__ u64 ffma2(u64 a, u64 b, u64 c) {
    u64 d;
    asm("fma.rn.f32x2 %0, %1, %2, %3;" : "=l"(d) : "l"(a), "l"(b), "l"(c));
    return d;
}
__device__ __forceinline__ u64 bcast2(float x) {
    u64 d;
    asm("mov.b64 %0, {%1, %1};" : "=l"(d) : "f"(x));
    return d;
}
__device__ __forceinline__ void unpack2(u64 v, float& lo, float& hi) {
    asm("mov.b64 {%0, %1}, %2;" : "=f"(lo), "=f"(hi) : "l"(v));
}

// One H=5 LSTM cell step, fully packed gate math.
// sW: WihT[5][20], WhhT at +100 (i/f/o rows pre-scaled 0.5); sB: pre-scaled fused bias[20].
__device__ __forceinline__ void cell(const float* __restrict__ sW,
                                     const float* __restrict__ sB,
                                     const float* __restrict__ in,
                                     float* __restrict__ h,
                                     float* __restrict__ c,
                                     bool commit) {
    u64 g[10];
    {
        const ulonglong2* b2 = reinterpret_cast<const ulonglong2*>(sB);
        #pragma unroll
        for (int q = 0; q < 5; q++) {
            ulonglong2 v = b2[q];               // LDS.128 -> two packed pairs
            g[2*q] = v.x; g[2*q+1] = v.y;
        }
    }
    #pragma unroll
    for (int k = 0; k < 5; k++) {
        u64 xk2 = bcast2(in[k]);
        const ulonglong2* w2 = reinterpret_cast<const ulonglong2*>(sW + k * 20);
        #pragma unroll
        for (int q = 0; q < 5; q++) {
            ulonglong2 w = w2[q];
            g[2*q]   = ffma2(w.x, xk2, g[2*q]);
            g[2*q+1] = ffma2(w.y, xk2, g[2*q+1]);
        }
    }
    #pragma unroll
    for (int k = 0; k < 5; k++) {
        u64 hk2 = bcast2(h[k]);
        const ulonglong2* u2 = reinterpret_cast<const ulonglong2*>(sW + 100 + k * 20);
        #pragma unroll
        for (int q = 0; q < 5; q++) {
            ulonglong2 u = u2[q];
            g[2*q]   = ffma2(u.x, hk2, g[2*q]);
            g[2*q+1] = ffma2(u.y, hk2, g[2*q+1]);
        }
    }
    float ga[20];
    #pragma unroll
    for (int q = 0; q < 10; q++) unpack2(g[q], ga[2*q], ga[2*q+1]);

    #pragma unroll
    for (int m = 0; m < 5; m++) {
        float ig = sigm_pre(ga[m]);
        float fg = sigm_pre(ga[5 + m]);
        float gg = tanh_fast(ga[10 + m]);
        float og = sigm_pre(ga[15 + m]);
        float cm = fmaf(fg, c[m], ig * gg);
        float hm = og * tanh_fast(cm);
        c[m] = commit ? cm : c[m];
        h[m] = commit ? hm : h[m];
    }
}

// Load one 4-timestep chunk (20 floats, 16B-aligned).
__device__ __forceinline__ void load_chunk(float* dst, const float* src) {
    const float4* s4 = reinterpret_cast<const float4*>(src);
    #pragma unroll
    for (int i = 0; i < 5; i++) {
        float4 v = __ldg(s4 + i);
        dst[4*i+0] = v.x; dst[4*i+1] = v.y;
        dst[4*i+2] = v.z; dst[4*i+3] = v.w;
    }
}

struct Params {
    const float *x1, *x2;
    const float *Wih1, *Whh1, *bih1, *bhh1;
    const float *Wih2a, *Whh2a, *bih2a, *bhh2a;
    const float *Wih2b, *Whh2b, *bih2b, *bhh2b;
    const float *W1, *b1, *W2, *b2, *W3, *b3, *W4, *b4, *W5, *b5;
    float* out;
    int B;
};

__global__ __launch_bounds__(BLK, 2)
void dynrnn_kernel(Params p) {
    __shared__ float s[S_TOTAL];
    const int tid = threadIdx.x;

    // ---- cooperative weight staging (transposed LSTM weights, role blocks) ----
    // sigmoid-gate rows (j<10 i/f, j>=15 o) pre-scaled by 0.5
    {
        const float* srcs[6] = { p.Wih1, p.Whh1, p.Wih2a, p.Whh2a, p.Wih2b, p.Whh2b };
        const int    offs[6] = { 0, 100, RSTRIDE, RSTRIDE+100, 2*RSTRIDE, 2*RSTRIDE+100 };
        for (int m = 0; m < 6; m++) {
            const float* W = srcs[m];
            int off = offs[m];
            for (int i = tid; i < 100; i += BLK) {
                int j = i / 5, k = i % 5;
                float sc = (j < 10 || j >= 15) ? 0.5f : 1.0f;
                s[off + k * 20 + j] = W[i] * sc;
            }
        }
        for (int i = tid; i < 20; i += BLK) {
            float sc = (i < 10 || i >= 15) ? 0.5f : 1.0f;
            s[0*RSTRIDE + 200 + i] = (p.bih1[i]  + p.bhh1[i])  * sc;
            s[1*RSTRIDE + 200 + i] = (p.bih2a[i] + p.bhh2a[i]) * sc;
            s[2*RSTRIDE + 200 + i] = (p.bih2b[i] + p.bhh2b[i]) * sc;
        }
        for (int i = tid; i < 640;  i += BLK) s[FW1 + i] = p.W1[i];
        for (int i = tid; i < 32;   i += BLK) s[FB1 + i] = p.b1[i];
        for (int i = tid; i < 1024; i += BLK) s[FW2 + i] = p.W2[i];
        for (int i = tid; i < 32;   i += BLK) s[FB2 + i] = p.b2[i];
        for (int i = tid; i < 512;  i += BLK) s[FW3 + i] = p.W3[i];
        for (int i = tid; i < 16;   i += BLK) s[FB3 + i] = p.b3[i];
        for (int i = tid; i < 256;  i += BLK) s[FW4 + i] = p.W4[i];
        for (int i = tid; i < 16;   i += BLK) s[FB4 + i] = p.b4[i];
        for (int i = tid; i < 80;   i += BLK) s[FW5 + i] = p.W5[i];
        for (int i = tid; i < 5;    i += BLK) s[FB5 + i] = p.b5[i];
    }
    __syncthreads();

    // ---- lane/role mapping: 3 lanes per element, 10 elements per warp ----
    const int l   = tid & 31;
    const int grp = l / 3;           // 0..9
    const int r   = l - 3 * grp;     // 0: lstm1, 1: lstm2a, 2: lstm2b
    const bool lane_ok = (l < 30);

    const int e = blockIdx.x * EPB + (tid >> 5) * 10 + grp;
    const bool valid = lane_ok && (e < p.B);
    const int ec = (e < p.B) ? e : (p.B - 1);

    const float* __restrict__ xp = ((r == 1) ? p.x2 : p.x1) + (size_t)ec * (TT * 5);
    const float* __restrict__ sW = s + r * RSTRIDE;
    const float* __restrict__ sB = sW + 200;
    const bool isr2 = (r == 2);

    float h[5], c[5], nh[5];
    #pragma unroll
    for (int m = 0; m < 5; m++) { h[m] = 0.0f; c[m] = 0.0f; nh[m] = 0.0f; }

    float A[20], Bb[20];
    load_chunk(A, xp);

    #pragma unroll 1
    for (int it = 0; it < 16; it++) {
        load_chunk(Bb, xp + (2 * it + 1) * 20);
        #pragma unroll
        for (int tl = 0; tl < 4; tl++) {
            float in[5];
            #pragma unroll
            for (int j = 0; j < 5; j++) in[j] = isr2 ? nh[j] : A[tl * 5 + j];
            bool commit = !(isr2 && (it == 0) && (tl == 0));
            cell(sW, sB, in, h, c, commit);
            #pragma unroll
            for (int j = 0; j < 5; j++) nh[j] = __shfl_up_sync(0xFFFFFFFFu, h[j], 1);
        }
        int ci = 2 * it + 2; if (ci > 31) ci = 31;
        load_chunk(A, xp + ci * 20);
        #pragma unroll
        for (int tl = 0; tl < 4; tl++) {
            float in[5];
            #pragma unroll
            for (int j = 0; j < 5; j++) in[j] = isr2 ? nh[j] : Bb[tl * 5 + j];
            cell(sW, sB, in, h, c, true);
            #pragma unroll
            for (int j = 0; j < 5; j++) nh[j] = __shfl_up_sync(0xFFFFFFFFu, h[j], 1);
        }
    }

    // role-2 drains the pipeline: final step consumes h2a(127)
    if (isr2) {
        cell(sW, sB, nh, h, c, true);
    }

    // ---- gather results onto role-0 lanes ----
    // last timestep inputs live in Bb[15..19] (chunk 31 = steps 124..127)
    float x2l[5], o2[5];
    #pragma unroll
    for (int j = 0; j < 5; j++) {
        x2l[j] = __shfl_down_sync(0xFFFFFFFFu, Bb[15 + j], 1);  // from role 1 (x2 last)
        o2[j]  = __shfl_down_sync(0xFFFFFFFFu, h[j], 2);        // from role 2 (out2)
    }

    if (valid && r == 0) {
        float a0[20];
        #pragma unroll
        for (int j = 0; j < 5; j++) {
            a0[j]      = Bb[15 + j];
            a0[5 + j]  = x2l[j];
            a0[10 + j] = h[j];
            a0[15 + j] = o2[j];
        }
        float a1[32];
        #pragma unroll
        for (int j = 0; j < 32; j++) {
            float acc = s[FB1 + j];
            #pragma unroll
            for (int k = 0; k < 20; k++) acc = fmaf(s[FW1 + j * 20 + k], a0[k], acc);
            a1[j] = fmaxf(acc, 0.0f);
        }
        float a2[32];
        #pragma unroll
        for (int j = 0; j < 32; j++) {
            float acc = s[FB2 + j];
            #pragma unroll
            for (int k = 0; k < 32; k++) acc = fmaf(s[FW2 + j * 32 + k], a1[k], acc);
            a2[j] = fmaxf(acc, 0.0f);
        }
        float a3[16];
        #pragma unroll
        for (int j = 0; j < 16; j++) {
            float acc = s[FB3 + j];
            #pragma unroll
            for (int k = 0; k < 32; k++) acc = fmaf(s[FW3 + j * 32 + k], a2[k], acc);
            a3[j] = fmaxf(acc, 0.0f);
        }
        float a4[16];
        #pragma unroll
        for (int j = 0; j < 16; j++) {
            float acc = s[FB4 + j];
            #pragma unroll
            for (int k = 0; k < 16; k++) acc = fmaf(s[FW4 + j * 16 + k], a3[k], acc);
            a4[j] = fmaxf(acc, 0.0f);
        }
        #pragma unroll
        for (int j = 0; j < 5; j++) {
            float acc = s[FB5 + j];
            #pragma unroll
            for (int k = 0; k < 16; k++) acc = fmaf(s[FW5 + j * 16 + k], a4[k], acc);
            p.out[(size_t)e * 5 + j] = acc;
        }
    }
}

extern "C" void kernel_launch(void* const* d_in, const int* in_sizes, int n_in,
                              void* d_out, int out_size) {
    Params p;
    p.x1    = (const float*)d_in[0];
    p.x2    = (const float*)d_in[1];
    p.Wih1  = (const float*)d_in[2];
    p.Whh1  = (const float*)d_in[3];
    p.bih1  = (const float*)d_in[4];
    p.bhh1  = (const float*)d_in[5];
    p.Wih2a = (const float*)d_in[6];
    p.Whh2a = (const float*)d_in[7];
    p.bih2a = (const float*)d_in[8];
    p.bhh2a = (const float*)d_in[9];
    p.Wih2b = (const float*)d_in[10];
    p.Whh2b = (const float*)d_in[11];
    p.bih2b = (const float*)d_in[12];
    p.bhh2b = (const float*)d_in[13];
    p.W1 = (const float*)d_in[14];  p.b1 = (const float*)d_in[15];
    p.W2 = (const float*)d_in[16];  p.b2 = (const float*)d_in[17];
    p.W3 = (const float*)d_in[18];  p.b3 = (const float*)d_in[19];
    p.W4 = (const float*)d_in[20];  p.b4 = (const float*)d_in[21];
    p.W5 = (const float*)d_in[22];  p.b5 = (const float*)d_in[23];
    p.out = (float*)d_out;
    p.B   = in_sizes[0] / (TT * 5);

    int grid = (p.B + EPB - 1) / EPB;   // 410 blocks for B=16384
    dynrnn_kernel<<<grid, BLK>>>(p);
}